// round 2
// baseline (speedup 1.0000x reference)
#include <cuda_runtime.h>
#include <math.h>

// ---------------------------------------------------------------------------
// ForceFieldPredictor: B=64, O=64, T=64, HID=128, 2 hidden layers.
//
// Kernel 1 (ffp_branch): per (b,o) row, branch MLP (5->128->128->128), then
//   fold with out_w into M[k][j] = branch_out[k]*out_w[k][j]  -> g_branchM.
// Kernel 2 (ffp_main): one CTA per (b,o) tile (64 t-rows):
//   features (capsule dist, masks, trunk_in[9], joint_in[15]) ->
//   trunk MLP via shared-tile fp32 GEMMs -> joint MLP -> fused epilogue.
// ---------------------------------------------------------------------------

#define PADR 132            // activation row stride (floats), bank-skewed

// smem layout (float offsets)
#define OFF_SW     0
#define OFF_ACT0   16384
#define OFF_ACT1   (16384 + 64*PADR)
#define OFF_FEAT   (16384 + 2*64*PADR)
#define OFF_JFEAT  (OFF_FEAT + 64*12)
#define OFF_MSH    (OFF_JFEAT + 64*16)
#define OFF_JW1    (OFF_MSH + 384)
#define SMEM_FLOATS (OFF_JW1 + 256)

__device__ float g_branchM[4096 * 384];   // [b*64+o][k*3+j]

// ---------------------------------------------------------------------------

__device__ __forceinline__ void stage_copy(float* dst, const float* src, int n, int tid)
{
    for (int i = tid * 4; i < n; i += 256 * 4)
        *(float4*)(dst + i) = *(const float4*)(src + i);
}

// C[64][128] = (relu?)(A[64][128]) @ W[128][128] + bias
// thread (ty,tx) in 16x16 grid: rows ty*4..+3, cols tx*8..+7
__device__ __forceinline__ void gemm_hidden(const float* __restrict__ actIn,
                                            float* __restrict__ actOut,
                                            const float* __restrict__ sW,
                                            const float* __restrict__ bias_g,
                                            int ty, int tx, bool relu_in)
{
    const int r0 = ty * 4, c0 = tx * 8;
    float acc[4][8];
    float4 bv0 = *(const float4*)(bias_g + c0);
    float4 bv1 = *(const float4*)(bias_g + c0 + 4);
    #pragma unroll
    for (int i = 0; i < 4; i++) {
        acc[i][0] = bv0.x; acc[i][1] = bv0.y; acc[i][2] = bv0.z; acc[i][3] = bv0.w;
        acc[i][4] = bv1.x; acc[i][5] = bv1.y; acc[i][6] = bv1.z; acc[i][7] = bv1.w;
    }
    for (int k = 0; k < 128; k += 4) {
        float4 av[4];
        #pragma unroll
        for (int i = 0; i < 4; i++) {
            float4 v = *(const float4*)(actIn + (r0 + i) * PADR + k);
            if (relu_in) {
                v.x = fmaxf(v.x, 0.f); v.y = fmaxf(v.y, 0.f);
                v.z = fmaxf(v.z, 0.f); v.w = fmaxf(v.w, 0.f);
            }
            av[i] = v;
        }
        #pragma unroll
        for (int kk = 0; kk < 4; kk++) {
            float4 w0 = *(const float4*)(sW + (k + kk) * 128 + c0);
            float4 w1 = *(const float4*)(sW + (k + kk) * 128 + c0 + 4);
            #pragma unroll
            for (int i = 0; i < 4; i++) {
                float a = (kk == 0) ? av[i].x : (kk == 1) ? av[i].y
                        : (kk == 2) ? av[i].z : av[i].w;
                acc[i][0] = fmaf(a, w0.x, acc[i][0]);
                acc[i][1] = fmaf(a, w0.y, acc[i][1]);
                acc[i][2] = fmaf(a, w0.z, acc[i][2]);
                acc[i][3] = fmaf(a, w0.w, acc[i][3]);
                acc[i][4] = fmaf(a, w1.x, acc[i][4]);
                acc[i][5] = fmaf(a, w1.y, acc[i][5]);
                acc[i][6] = fmaf(a, w1.z, acc[i][6]);
                acc[i][7] = fmaf(a, w1.w, acc[i][7]);
            }
        }
    }
    #pragma unroll
    for (int i = 0; i < 4; i++) {
        *(float4*)(actOut + (r0 + i) * PADR + c0)     = make_float4(acc[i][0], acc[i][1], acc[i][2], acc[i][3]);
        *(float4*)(actOut + (r0 + i) * PADR + c0 + 4) = make_float4(acc[i][4], acc[i][5], acc[i][6], acc[i][7]);
    }
}

// C[64][128] = feat[64][K] @ W[K][128] + bias (no input relu)
__device__ __forceinline__ void gemm_input(const float* __restrict__ feat, int fstride, int K,
                                           float* __restrict__ actOut,
                                           const float* __restrict__ sWin,
                                           const float* __restrict__ bias_g,
                                           int ty, int tx)
{
    const int r0 = ty * 4, c0 = tx * 8;
    float acc[4][8];
    float4 bv0 = *(const float4*)(bias_g + c0);
    float4 bv1 = *(const float4*)(bias_g + c0 + 4);
    #pragma unroll
    for (int i = 0; i < 4; i++) {
        acc[i][0] = bv0.x; acc[i][1] = bv0.y; acc[i][2] = bv0.z; acc[i][3] = bv0.w;
        acc[i][4] = bv1.x; acc[i][5] = bv1.y; acc[i][6] = bv1.z; acc[i][7] = bv1.w;
    }
    for (int k = 0; k < K; k++) {
        float4 w0 = *(const float4*)(sWin + k * 128 + c0);
        float4 w1 = *(const float4*)(sWin + k * 128 + c0 + 4);
        #pragma unroll
        for (int i = 0; i < 4; i++) {
            float a = feat[(r0 + i) * fstride + k];
            acc[i][0] = fmaf(a, w0.x, acc[i][0]);
            acc[i][1] = fmaf(a, w0.y, acc[i][1]);
            acc[i][2] = fmaf(a, w0.z, acc[i][2]);
            acc[i][3] = fmaf(a, w0.w, acc[i][3]);
            acc[i][4] = fmaf(a, w1.x, acc[i][4]);
            acc[i][5] = fmaf(a, w1.y, acc[i][5]);
            acc[i][6] = fmaf(a, w1.z, acc[i][6]);
            acc[i][7] = fmaf(a, w1.w, acc[i][7]);
        }
    }
    #pragma unroll
    for (int i = 0; i < 4; i++) {
        *(float4*)(actOut + (r0 + i) * PADR + c0)     = make_float4(acc[i][0], acc[i][1], acc[i][2], acc[i][3]);
        *(float4*)(actOut + (r0 + i) * PADR + c0 + 4) = make_float4(acc[i][4], acc[i][5], acc[i][6], acc[i][7]);
    }
}

__device__ __forceinline__ float segdist(float px, float py, float ax, float ay,
                                         float abx, float aby, float s)
{
    float t = ((px - ax) * abx + (py - ay) * aby) / s;
    t = fminf(fmaxf(t, 0.f), 1.f);
    float dx = px - (ax + t * abx);
    float dy = py - (ay + t * aby);
    return sqrtf(dx * dx + dy * dy);
}

// ---------------------------------------------------------------------------
// Kernel 1: branch precompute. grid = 64 (one block per b), 64 o-rows per tile.
// ---------------------------------------------------------------------------
extern "C" __global__ void __launch_bounds__(256, 1)
ffp_branch(const float* __restrict__ init_x,
           const float* __restrict__ branch_w0, const float* __restrict__ branch_b0,
           const float* __restrict__ branch_ws, const float* __restrict__ branch_bs,
           const float* __restrict__ out_w)
{
    extern __shared__ float sm[];
    float* sW   = sm + OFF_SW;
    float* act0 = sm + OFF_ACT0;
    float* act1 = sm + OFF_ACT1;
    float* feat = sm + OFF_FEAT;   // [64][4] : x2,x3,x4
    const int tid = threadIdx.x, ty = tid >> 4, tx = tid & 15;
    const int b = blockIdx.x;

    // branch_in = [0,0,x2,x3,x4] -> only rows 2..4 of w0 matter
    stage_copy(sW, branch_w0 + 2 * 128, 384, tid);
    if (tid < 64) {
        const float* ix = init_x + (b * 64 + tid) * 9;
        feat[tid * 4 + 0] = ix[2];
        feat[tid * 4 + 1] = ix[3];
        feat[tid * 4 + 2] = ix[4];
    }
    __syncthreads();
    gemm_input(feat, 4, 3, act0, sW, branch_b0, ty, tx);
    __syncthreads();
    stage_copy(sW, branch_ws, 16384, tid);
    __syncthreads();
    gemm_hidden(act0, act1, sW, branch_bs, ty, tx, true);
    __syncthreads();
    stage_copy(sW, branch_ws + 16384, 16384, tid);
    __syncthreads();
    gemm_hidden(act1, act0, sW, branch_bs + 128, ty, tx, true);
    __syncthreads();

    // M[k][j] = branch_out[k] * out_w[k][j]
    for (int idx = tid; idx < 64 * 384; idx += 256) {
        int o = idx / 384;
        int r = idx - o * 384;
        int k = r / 3;
        int j = r - k * 3;
        g_branchM[(b * 64 + o) * 384 + r] = act0[o * PADR + k] * out_w[k * 3 + j];
    }
}

// ---------------------------------------------------------------------------
// Kernel 2: main. grid = 4096 (one block per (b,o)); 64 t-rows per tile.
// ---------------------------------------------------------------------------
extern "C" __global__ void __launch_bounds__(256, 1)
ffp_main(const float* __restrict__ init_x,  const float* __restrict__ query_x,
         const float* __restrict__ init_v,  const float* __restrict__ query_v,
         const float* __restrict__ init_av, const float* __restrict__ query_av,
         const float* __restrict__ trunk_w0, const float* __restrict__ trunk_b0,
         const float* __restrict__ trunk_ws, const float* __restrict__ trunk_bs,
         const float* __restrict__ out_b,
         const float* __restrict__ spring_w0, const float* __restrict__ spring_b0,
         const float* __restrict__ spring_w1, const float* __restrict__ spring_b1,
         const float* __restrict__ joint_w0, const float* __restrict__ joint_b0,
         const float* __restrict__ joint_w1, const float* __restrict__ joint_b1,
         float* __restrict__ out)
{
    extern __shared__ float sm[];
    float* sW    = sm + OFF_SW;
    float* act0  = sm + OFF_ACT0;
    float* act1  = sm + OFF_ACT1;
    float* feat  = sm + OFF_FEAT;    // [64][12]: trunk_in[9], maskD, maskJ, maskS
    float* jfeat = sm + OFF_JFEAT;   // [64][16]: joint_in[15]
    float* msh   = sm + OFF_MSH;     // [128*3] branch (x) out_w
    float* jw1s  = sm + OFF_JW1;     // [128*2]
    const int tid = threadIdx.x, ty = tid >> 4, tx = tid & 15;
    const int bo = blockIdx.x;
    const int b = bo >> 6;

    stage_copy(sW, trunk_w0, 1152, tid);
    stage_copy(msh, g_branchM + bo * 384, 384, tid);
    stage_copy(jw1s, joint_w1, 256, tid);

    if (tid < 64) {
        const int t = tid;
        const float* ix = init_x + bo * 9;
        const float* qx = query_x + (b * 64 + t) * 9;
        float i2 = ix[2], i3 = ix[3], i4 = ix[4], i7 = ix[7], i8 = ix[8];
        float q2 = qx[2], q3 = qx[3], q4 = qx[4], q7 = qx[7], q8 = qx[8];
        float relx = qx[0] - ix[0], rely = qx[1] - ix[1];
        float ivx = init_v[bo * 2 + 0], ivy = init_v[bo * 2 + 1];
        float qvx = query_v[(b * 64 + t) * 2 + 0] - ivx;
        float qvy = query_v[(b * 64 + t) * 2 + 1] - ivy;
        float iav = init_av[bo];
        float qav = query_av[b * 64 + t] - iav;

        // capsule distance
        float sn1, cs1; sincosf(i3 * 100.f, &sn1, &cs1);
        float sn2, cs2; sincosf(q3 * 100.f, &sn2, &cs2);
        float hh1 = i2 * 0.5f, hh2 = q2 * 0.5f;
        float o1x = hh1 * cs1, o1y = hh1 * sn1;
        float o2x = hh2 * cs2, o2y = hh2 * sn2;
        float ab1x = 2.f * o1x, ab1y = 2.f * o1y;
        float ab2x = 2.f * o2x, ab2y = 2.f * o2y;
        float ss1 = ab1x * ab1x + ab1y * ab1y + 1e-8f;
        float ss2 = ab2x * ab2x + ab2y * ab2y + 1e-8f;
        float A1x = -o1x, A1y = -o1y, B1x = o1x, B1y = o1y;
        float A2x = relx - o2x, A2y = rely - o2y;
        float B2x = relx + o2x, B2y = rely + o2y;
        float d1 = segdist(A2x, A2y, A1x, A1y, ab1x, ab1y, ss1);
        float d2 = segdist(B2x, B2y, A1x, A1y, ab1x, ab1y, ss1);
        float d3 = segdist(A1x, A1y, A2x, A2y, ab2x, ab2y, ss2);
        float d4 = segdist(B1x, B1y, A2x, A2y, ab2x, ab2y, ss2);
        float dist = fminf(fminf(d1, d2), fminf(d3, d4)) - i4 - q4;
        float maskD = (dist <= 0.f) ? 1.f : 0.f;

        feat[t * 12 + 0] = relx;
        feat[t * 12 + 1] = rely;
        feat[t * 12 + 2] = q2;
        feat[t * 12 + 3] = q3;
        feat[t * 12 + 4] = q4;
        feat[t * 12 + 5] = qvx;
        feat[t * 12 + 6] = qvy;
        feat[t * 12 + 7] = qav;
        feat[t * 12 + 8] = dist * maskD * 100.f;
        feat[t * 12 + 9] = maskD;
        float ti = truncf(i7), tq = truncf(q7);
        feat[t * 12 + 10] = (ti == tq && i7 > 0.f) ? 1.f : 0.f;
        feat[t * 12 + 11] = (i8 == q8 && i8 > 0.f) ? 1.f : 0.f;

        jfeat[t * 16 + 0]  = 0.f;
        jfeat[t * 16 + 1]  = 0.f;
        jfeat[t * 16 + 2]  = i2;
        jfeat[t * 16 + 3]  = i3;
        jfeat[t * 16 + 4]  = i4;
        jfeat[t * 16 + 5]  = relx;
        jfeat[t * 16 + 6]  = rely;
        jfeat[t * 16 + 7]  = q2;
        jfeat[t * 16 + 8]  = q3;
        jfeat[t * 16 + 9]  = q4;
        jfeat[t * 16 + 10] = qvx;
        jfeat[t * 16 + 11] = qvy;
        jfeat[t * 16 + 12] = iav;
        jfeat[t * 16 + 13] = qav;
        jfeat[t * 16 + 14] = i7 - ti;
    }
    __syncthreads();

    // trunk layer 0: 9 -> 128
    gemm_input(feat, 12, 9, act0, sW, trunk_b0, ty, tx);
    __syncthreads();
    stage_copy(sW, trunk_ws, 16384, tid);
    __syncthreads();
    gemm_hidden(act0, act1, sW, trunk_bs, ty, tx, true);
    __syncthreads();
    stage_copy(sW, trunk_ws + 16384, 16384, tid);
    __syncthreads();
    gemm_hidden(act1, act0, sW, trunk_bs + 128, ty, tx, true);   // h2 -> act0
    __syncthreads();
    stage_copy(sW, joint_w0, 1920, tid);
    __syncthreads();
    gemm_input(jfeat, 16, 15, act1, sW, joint_b0, ty, tx);       // joint hidden (pre-relu) -> act1
    __syncthreads();

    // epilogue: thread = (row, part); part 0..2 computes force component
    {
        const int row = tid >> 2, part = tid & 3;
        if (part < 3) {
            const float* h = act0 + row * PADR;
            float f = 0.f;
            #pragma unroll 4
            for (int k = 0; k < 128; k++)
                f = fmaf(h[k], msh[k * 3 + part], f);
            f = (f + out_b[part]) * feat[row * 12 + 9];
            if (part < 2) {
                float maskJ = feat[row * 12 + 10];
                if (maskJ > 0.f) {
                    const float* jh = act1 + row * PADR;
                    float jf = joint_b1[part];
                    #pragma unroll 4
                    for (int k = 0; k < 128; k++)
                        jf = fmaf(fmaxf(jh[k], 0.f), jw1s[k * 2 + part], jf);
                    f += jf;
                }
                float maskS = feat[row * 12 + 11];
                if (maskS > 0.f) {
                    float rx = feat[row * 12 + 0], ry = feat[row * 12 + 1];
                    float len = sqrtf(rx * rx + ry * ry);
                    float sf = spring_b1[0];
                    for (int k = 0; k < 128; k++)
                        sf = fmaf(fmaxf(fmaf(len, spring_w0[k], spring_b0[k]), 0.f),
                                  spring_w1[k], sf);
                    float dv = ((part == 0) ? -rx : -ry) / (len + 1e-8f);
                    f = fmaf(sf, dv, f);
                }
            }
            out[(bo * 64 + row) * 3 + part] = f;
        }
    }
}

// ---------------------------------------------------------------------------

extern "C" void kernel_launch(void* const* d_in, const int* in_sizes, int n_in,
                              void* d_out, int out_size)
{
    const float* init_x    = (const float*)d_in[0];
    const float* query_x   = (const float*)d_in[1];
    const float* init_v    = (const float*)d_in[2];
    const float* query_v   = (const float*)d_in[3];
    const float* init_av   = (const float*)d_in[4];
    const float* query_av  = (const float*)d_in[5];
    const float* trunk_w0  = (const float*)d_in[6];
    const float* trunk_b0  = (const float*)d_in[7];
    const float* trunk_ws  = (const float*)d_in[8];
    const float* trunk_bs  = (const float*)d_in[9];
    const float* branch_w0 = (const float*)d_in[10];
    const float* branch_b0 = (const float*)d_in[11];
    const float* branch_ws = (const float*)d_in[12];
    const float* branch_bs = (const float*)d_in[13];
    const float* out_w     = (const float*)d_in[14];
    const float* out_b     = (const float*)d_in[15];
    const float* spring_w0 = (const float*)d_in[16];
    const float* spring_b0 = (const float*)d_in[17];
    const float* spring_w1 = (const float*)d_in[18];
    const float* spring_b1 = (const float*)d_in[19];
    const float* joint_w0  = (const float*)d_in[20];
    const float* joint_b0  = (const float*)d_in[21];
    const float* joint_w1  = (const float*)d_in[22];
    const float* joint_b1  = (const float*)d_in[23];
    float* out = (float*)d_out;

    const int smem = SMEM_FLOATS * sizeof(float);
    cudaFuncSetAttribute(ffp_branch, cudaFuncAttributeMaxDynamicSharedMemorySize, smem);
    cudaFuncSetAttribute(ffp_main,   cudaFuncAttributeMaxDynamicSharedMemorySize, smem);

    ffp_branch<<<64, 256, smem>>>(init_x, branch_w0, branch_b0, branch_ws, branch_bs, out_w);
    ffp_main<<<4096, 256, smem>>>(init_x, query_x, init_v, query_v, init_av, query_av,
                                  trunk_w0, trunk_b0, trunk_ws, trunk_bs,
                                  out_b,
                                  spring_w0, spring_b0, spring_w1, spring_b1,
                                  joint_w0, joint_b0, joint_w1, joint_b1,
                                  out);
}

// round 3
// speedup vs baseline: 1.2487x; 1.2487x over previous
#include <cuda_runtime.h>
#include <math.h>

// ---------------------------------------------------------------------------
// ForceFieldPredictor: B=64, O=64, T=64, HID=128, 2 hidden layers.
//
// R3: persistent ffp_main (weights resident in smem, grid = #SMs, tile loop)
//     + packed fma.rn.f32x2 inner GEMM (halves fma-class issue count).
// ---------------------------------------------------------------------------

#define PADR 132            // activation row stride (floats), bank-skewed

// ---- main-kernel smem layout (float offsets) ----
#define M_W1    0                       // 16384  trunk hidden W1
#define M_W2    16384                   // 16384  trunk hidden W2
#define M_W0    32768                   // 1152   trunk input W0 (9x128)
#define M_JW0   33920                   // 1920   joint input W0 (15x128)
#define M_ACT0  35840                   // 64*PADR
#define M_ACT1  (35840 + 64*PADR)       // 64*PADR
#define M_FEAT  (35840 + 2*64*PADR)     // 64*12
#define M_JFEAT (M_FEAT + 64*12)        // 64*16
#define M_MSH   (M_JFEAT + 64*16)       // 384
#define M_JW1   (M_MSH + 384)           // 256
#define M_TOTAL (M_JW1 + 256)           // 55168 floats = 220672 B

// ---- branch-kernel smem layout ----
#define B_W     0
#define B_ACT0  16384
#define B_ACT1  (16384 + 64*PADR)
#define B_FEAT  (16384 + 2*64*PADR)
#define B_TOTAL (B_FEAT + 64*4)

__device__ float g_branchM[4096 * 384];   // [b*64+o][k*3+j]

typedef unsigned long long ull;

// packed fp32x2 FMA: d = a*b + d, lanewise (sm_100+ PTX)
#define FMA2(d, a, b) asm("fma.rn.f32x2 %0, %1, %2, %0;" : "+l"(d) : "l"(a), "l"(b))
// splat one fp32 (as bits) into both lanes of a 64-bit pair
#define SPLAT2(d, s)  asm("mov.b64 %0, {%1, %1};" : "=l"(d) : "r"(s))

// ---------------------------------------------------------------------------

__device__ __forceinline__ void stage_copy(float* dst, const float* src, int n, int tid)
{
    for (int i = tid * 4; i < n; i += 256 * 4)
        *(float4*)(dst + i) = *(const float4*)(src + i);
}

// C[64][128] = (relu?)(A[64][128]) @ W[128][128] + bias, packed f32x2 inner.
// thread (ty,tx): rows ty*4..+3, cols tx*8..+7 (4 col-pairs).
__device__ __forceinline__ void gemm_hidden_f2(const float* __restrict__ actIn,
                                               float* __restrict__ actOut,
                                               const float* __restrict__ sW,
                                               const float* __restrict__ bias_g,
                                               int ty, int tx, bool relu_in)
{
    const int r0 = ty * 4, c0 = tx * 8;
    ull acc[4][4];
    {
        ulonglong2 b0 = *(const ulonglong2*)(bias_g + c0);
        ulonglong2 b1 = *(const ulonglong2*)(bias_g + c0 + 4);
        #pragma unroll
        for (int i = 0; i < 4; i++) {
            acc[i][0] = b0.x; acc[i][1] = b0.y;
            acc[i][2] = b1.x; acc[i][3] = b1.y;
        }
    }
    for (int k = 0; k < 128; k += 4) {
        float4 av[4];
        #pragma unroll
        for (int i = 0; i < 4; i++) {
            float4 v = *(const float4*)(actIn + (r0 + i) * PADR + k);
            if (relu_in) {
                v.x = fmaxf(v.x, 0.f); v.y = fmaxf(v.y, 0.f);
                v.z = fmaxf(v.z, 0.f); v.w = fmaxf(v.w, 0.f);
            }
            av[i] = v;
        }
        #pragma unroll
        for (int kk = 0; kk < 4; kk++) {
            ulonglong2 w0 = *(const ulonglong2*)(sW + (k + kk) * 128 + c0);
            ulonglong2 w1 = *(const ulonglong2*)(sW + (k + kk) * 128 + c0 + 4);
            #pragma unroll
            for (int i = 0; i < 4; i++) {
                float a = (kk == 0) ? av[i].x : (kk == 1) ? av[i].y
                        : (kk == 2) ? av[i].z : av[i].w;
                ull a2;
                SPLAT2(a2, __float_as_uint(a));
                FMA2(acc[i][0], a2, w0.x);
                FMA2(acc[i][1], a2, w0.y);
                FMA2(acc[i][2], a2, w1.x);
                FMA2(acc[i][3], a2, w1.y);
            }
        }
    }
    #pragma unroll
    for (int i = 0; i < 4; i++) {
        ulonglong2 s0; s0.x = acc[i][0]; s0.y = acc[i][1];
        ulonglong2 s1; s1.x = acc[i][2]; s1.y = acc[i][3];
        *(ulonglong2*)(actOut + (r0 + i) * PADR + c0)     = s0;
        *(ulonglong2*)(actOut + (r0 + i) * PADR + c0 + 4) = s1;
    }
}

// C[64][128] = feat[64][K] @ W[K][128] + bias (no input relu), scalar fp32.
__device__ __forceinline__ void gemm_input(const float* __restrict__ feat, int fstride, int K,
                                           float* __restrict__ actOut,
                                           const float* __restrict__ sWin,
                                           const float* __restrict__ bias_g,
                                           int ty, int tx)
{
    const int r0 = ty * 4, c0 = tx * 8;
    float acc[4][8];
    float4 bv0 = *(const float4*)(bias_g + c0);
    float4 bv1 = *(const float4*)(bias_g + c0 + 4);
    #pragma unroll
    for (int i = 0; i < 4; i++) {
        acc[i][0] = bv0.x; acc[i][1] = bv0.y; acc[i][2] = bv0.z; acc[i][3] = bv0.w;
        acc[i][4] = bv1.x; acc[i][5] = bv1.y; acc[i][6] = bv1.z; acc[i][7] = bv1.w;
    }
    for (int k = 0; k < K; k++) {
        float4 w0 = *(const float4*)(sWin + k * 128 + c0);
        float4 w1 = *(const float4*)(sWin + k * 128 + c0 + 4);
        #pragma unroll
        for (int i = 0; i < 4; i++) {
            float a = feat[(r0 + i) * fstride + k];
            acc[i][0] = fmaf(a, w0.x, acc[i][0]);
            acc[i][1] = fmaf(a, w0.y, acc[i][1]);
            acc[i][2] = fmaf(a, w0.z, acc[i][2]);
            acc[i][3] = fmaf(a, w0.w, acc[i][3]);
            acc[i][4] = fmaf(a, w1.x, acc[i][4]);
            acc[i][5] = fmaf(a, w1.y, acc[i][5]);
            acc[i][6] = fmaf(a, w1.z, acc[i][6]);
            acc[i][7] = fmaf(a, w1.w, acc[i][7]);
        }
    }
    #pragma unroll
    for (int i = 0; i < 4; i++) {
        *(float4*)(actOut + (r0 + i) * PADR + c0)     = make_float4(acc[i][0], acc[i][1], acc[i][2], acc[i][3]);
        *(float4*)(actOut + (r0 + i) * PADR + c0 + 4) = make_float4(acc[i][4], acc[i][5], acc[i][6], acc[i][7]);
    }
}

__device__ __forceinline__ float segdist(float px, float py, float ax, float ay,
                                         float abx, float aby, float s)
{
    float t = ((px - ax) * abx + (py - ay) * aby) / s;
    t = fminf(fmaxf(t, 0.f), 1.f);
    float dx = px - (ax + t * abx);
    float dy = py - (ay + t * aby);
    return sqrtf(dx * dx + dy * dy);
}

// ---------------------------------------------------------------------------
// Kernel 1: branch precompute. grid = 64 (one block per b), 64 o-rows.
// ---------------------------------------------------------------------------
extern "C" __global__ void __launch_bounds__(256, 1)
ffp_branch(const float* __restrict__ init_x,
           const float* __restrict__ branch_w0, const float* __restrict__ branch_b0,
           const float* __restrict__ branch_ws, const float* __restrict__ branch_bs,
           const float* __restrict__ out_w)
{
    extern __shared__ float sm[];
    float* sW   = sm + B_W;
    float* act0 = sm + B_ACT0;
    float* act1 = sm + B_ACT1;
    float* feat = sm + B_FEAT;   // [64][4]: x2,x3,x4
    const int tid = threadIdx.x, ty = tid >> 4, tx = tid & 15;
    const int b = blockIdx.x;

    // branch_in = [0,0,x2,x3,x4] -> only rows 2..4 of w0 matter
    stage_copy(sW, branch_w0 + 2 * 128, 384, tid);
    if (tid < 64) {
        const float* ix = init_x + (b * 64 + tid) * 9;
        feat[tid * 4 + 0] = ix[2];
        feat[tid * 4 + 1] = ix[3];
        feat[tid * 4 + 2] = ix[4];
    }
    __syncthreads();
    gemm_input(feat, 4, 3, act0, sW, branch_b0, ty, tx);
    __syncthreads();
    stage_copy(sW, branch_ws, 16384, tid);
    __syncthreads();
    gemm_hidden_f2(act0, act1, sW, branch_bs, ty, tx, true);
    __syncthreads();
    stage_copy(sW, branch_ws + 16384, 16384, tid);
    __syncthreads();
    gemm_hidden_f2(act1, act0, sW, branch_bs + 128, ty, tx, true);
    __syncthreads();

    // M[k][j] = branch_out[k] * out_w[k][j]
    for (int idx = tid; idx < 64 * 384; idx += 256) {
        int o = idx / 384;
        int r = idx - o * 384;
        int k = r / 3;
        int j = r - k * 3;
        g_branchM[(b * 64 + o) * 384 + r] = act0[o * PADR + k] * out_w[k * 3 + j];
    }
}

// ---------------------------------------------------------------------------
// Kernel 2: persistent main. grid = #SMs; each CTA loops over (b,o) tiles.
// ---------------------------------------------------------------------------
extern "C" __global__ void __launch_bounds__(256, 1)
ffp_main(const float* __restrict__ init_x,  const float* __restrict__ query_x,
         const float* __restrict__ init_v,  const float* __restrict__ query_v,
         const float* __restrict__ init_av, const float* __restrict__ query_av,
         const float* __restrict__ trunk_w0, const float* __restrict__ trunk_b0,
         const float* __restrict__ trunk_ws, const float* __restrict__ trunk_bs,
         const float* __restrict__ out_b,
         const float* __restrict__ spring_w0, const float* __restrict__ spring_b0,
         const float* __restrict__ spring_w1, const float* __restrict__ spring_b1,
         const float* __restrict__ joint_w0, const float* __restrict__ joint_b0,
         const float* __restrict__ joint_w1, const float* __restrict__ joint_b1,
         float* __restrict__ out)
{
    extern __shared__ float sm[];
    float* sW1   = sm + M_W1;
    float* sW2   = sm + M_W2;
    float* sW0   = sm + M_W0;
    float* sJW0  = sm + M_JW0;
    float* act0  = sm + M_ACT0;
    float* act1  = sm + M_ACT1;
    float* feat  = sm + M_FEAT;    // [64][12]: trunk_in[9], maskD, maskJ, maskS
    float* jfeat = sm + M_JFEAT;   // [64][16]: joint_in[15]
    float* msh   = sm + M_MSH;     // [128*3] branch (x) out_w
    float* jw1s  = sm + M_JW1;     // [128*2]
    const int tid = threadIdx.x, ty = tid >> 4, tx = tid & 15;

    // ---- stage all shared weights ONCE ----
    stage_copy(sW1,  trunk_ws,          16384, tid);
    stage_copy(sW2,  trunk_ws + 16384,  16384, tid);
    stage_copy(sW0,  trunk_w0,          1152,  tid);
    stage_copy(sJW0, joint_w0,          1920,  tid);
    stage_copy(jw1s, joint_w1,          256,   tid);
    __syncthreads();

    for (int bo = blockIdx.x; bo < 4096; bo += gridDim.x) {
        const int b = bo >> 6;

        stage_copy(msh, g_branchM + bo * 384, 384, tid);

        if (tid < 64) {
            const int t = tid;
            const float* ix = init_x + bo * 9;
            const float* qx = query_x + (b * 64 + t) * 9;
            float i2 = ix[2], i3 = ix[3], i4 = ix[4], i7 = ix[7], i8 = ix[8];
            float q2 = qx[2], q3 = qx[3], q4 = qx[4], q7 = qx[7], q8 = qx[8];
            float relx = qx[0] - ix[0], rely = qx[1] - ix[1];
            float ivx = init_v[bo * 2 + 0], ivy = init_v[bo * 2 + 1];
            float qvx = query_v[(b * 64 + t) * 2 + 0] - ivx;
            float qvy = query_v[(b * 64 + t) * 2 + 1] - ivy;
            float iav = init_av[bo];
            float qav = query_av[b * 64 + t] - iav;

            // capsule distance
            float sn1, cs1; sincosf(i3 * 100.f, &sn1, &cs1);
            float sn2, cs2; sincosf(q3 * 100.f, &sn2, &cs2);
            float hh1 = i2 * 0.5f, hh2 = q2 * 0.5f;
            float o1x = hh1 * cs1, o1y = hh1 * sn1;
            float o2x = hh2 * cs2, o2y = hh2 * sn2;
            float ab1x = 2.f * o1x, ab1y = 2.f * o1y;
            float ab2x = 2.f * o2x, ab2y = 2.f * o2y;
            float ss1 = ab1x * ab1x + ab1y * ab1y + 1e-8f;
            float ss2 = ab2x * ab2x + ab2y * ab2y + 1e-8f;
            float A1x = -o1x, A1y = -o1y, B1x = o1x, B1y = o1y;
            float A2x = relx - o2x, A2y = rely - o2y;
            float B2x = relx + o2x, B2y = rely + o2y;
            float d1 = segdist(A2x, A2y, A1x, A1y, ab1x, ab1y, ss1);
            float d2 = segdist(B2x, B2y, A1x, A1y, ab1x, ab1y, ss1);
            float d3 = segdist(A1x, A1y, A2x, A2y, ab2x, ab2y, ss2);
            float d4 = segdist(B1x, B1y, A2x, A2y, ab2x, ab2y, ss2);
            float dist = fminf(fminf(d1, d2), fminf(d3, d4)) - i4 - q4;
            float maskD = (dist <= 0.f) ? 1.f : 0.f;

            feat[t * 12 + 0] = relx;
            feat[t * 12 + 1] = rely;
            feat[t * 12 + 2] = q2;
            feat[t * 12 + 3] = q3;
            feat[t * 12 + 4] = q4;
            feat[t * 12 + 5] = qvx;
            feat[t * 12 + 6] = qvy;
            feat[t * 12 + 7] = qav;
            feat[t * 12 + 8] = dist * maskD * 100.f;
            feat[t * 12 + 9] = maskD;
            float ti = truncf(i7), tq = truncf(q7);
            feat[t * 12 + 10] = (ti == tq && i7 > 0.f) ? 1.f : 0.f;
            feat[t * 12 + 11] = (i8 == q8 && i8 > 0.f) ? 1.f : 0.f;

            jfeat[t * 16 + 0]  = 0.f;
            jfeat[t * 16 + 1]  = 0.f;
            jfeat[t * 16 + 2]  = i2;
            jfeat[t * 16 + 3]  = i3;
            jfeat[t * 16 + 4]  = i4;
            jfeat[t * 16 + 5]  = relx;
            jfeat[t * 16 + 6]  = rely;
            jfeat[t * 16 + 7]  = q2;
            jfeat[t * 16 + 8]  = q3;
            jfeat[t * 16 + 9]  = q4;
            jfeat[t * 16 + 10] = qvx;
            jfeat[t * 16 + 11] = qvy;
            jfeat[t * 16 + 12] = iav;
            jfeat[t * 16 + 13] = qav;
            jfeat[t * 16 + 14] = i7 - ti;
        }
        __syncthreads();

        gemm_input(feat, 12, 9, act0, sW0, trunk_b0, ty, tx);        // trunk L0
        __syncthreads();
        gemm_hidden_f2(act0, act1, sW1, trunk_bs, ty, tx, true);     // trunk H1
        __syncthreads();
        gemm_hidden_f2(act1, act0, sW2, trunk_bs + 128, ty, tx, true); // trunk H2 -> act0
        __syncthreads();
        gemm_input(jfeat, 16, 15, act1, sJW0, joint_b0, ty, tx);     // joint hidden (pre-relu) -> act1
        __syncthreads();

        // epilogue: thread = (row, part); part 0..2 computes one force comp
        {
            const int row = tid >> 2, part = tid & 3;
            if (part < 3) {
                const float* h = act0 + row * PADR;
                float f0 = 0.f, f1 = 0.f, f2 = 0.f, f3 = 0.f;
                #pragma unroll
                for (int k = 0; k < 128; k += 4) {
                    f0 = fmaf(h[k],     msh[(k)     * 3 + part], f0);
                    f1 = fmaf(h[k + 1], msh[(k + 1) * 3 + part], f1);
                    f2 = fmaf(h[k + 2], msh[(k + 2) * 3 + part], f2);
                    f3 = fmaf(h[k + 3], msh[(k + 3) * 3 + part], f3);
                }
                float f = ((f0 + f1) + (f2 + f3) + out_b[part]) * feat[row * 12 + 9];
                if (part < 2) {
                    float maskJ = feat[row * 12 + 10];
                    if (maskJ > 0.f) {
                        const float* jh = act1 + row * PADR;
                        float j0 = 0.f, j1 = 0.f, j2 = 0.f, j3 = 0.f;
                        #pragma unroll
                        for (int k = 0; k < 128; k += 4) {
                            j0 = fmaf(fmaxf(jh[k],     0.f), jw1s[(k)     * 2 + part], j0);
                            j1 = fmaf(fmaxf(jh[k + 1], 0.f), jw1s[(k + 1) * 2 + part], j1);
                            j2 = fmaf(fmaxf(jh[k + 2], 0.f), jw1s[(k + 2) * 2 + part], j2);
                            j3 = fmaf(fmaxf(jh[k + 3], 0.f), jw1s[(k + 3) * 2 + part], j3);
                        }
                        f += (j0 + j1) + (j2 + j3) + joint_b1[part];
                    }
                    float maskS = feat[row * 12 + 11];
                    if (maskS > 0.f) {
                        float rx = feat[row * 12 + 0], ry = feat[row * 12 + 1];
                        float len = sqrtf(rx * rx + ry * ry);
                        float sf = spring_b1[0];
                        for (int k = 0; k < 128; k++)
                            sf = fmaf(fmaxf(fmaf(len, spring_w0[k], spring_b0[k]), 0.f),
                                      spring_w1[k], sf);
                        float dv = ((part == 0) ? -rx : -ry) / (len + 1e-8f);
                        f = fmaf(sf, dv, f);
                    }
                }
                out[(bo * 64 + row) * 3 + part] = f;
            }
        }
        __syncthreads();   // protect feat/act/msh before next tile
    }
}

// ---------------------------------------------------------------------------

extern "C" void kernel_launch(void* const* d_in, const int* in_sizes, int n_in,
                              void* d_out, int out_size)
{
    const float* init_x    = (const float*)d_in[0];
    const float* query_x   = (const float*)d_in[1];
    const float* init_v    = (const float*)d_in[2];
    const float* query_v   = (const float*)d_in[3];
    const float* init_av   = (const float*)d_in[4];
    const float* query_av  = (const float*)d_in[5];
    const float* trunk_w0  = (const float*)d_in[6];
    const float* trunk_b0  = (const float*)d_in[7];
    const float* trunk_ws  = (const float*)d_in[8];
    const float* trunk_bs  = (const float*)d_in[9];
    const float* branch_w0 = (const float*)d_in[10];
    const float* branch_b0 = (const float*)d_in[11];
    const float* branch_ws = (const float*)d_in[12];
    const float* branch_bs = (const float*)d_in[13];
    const float* out_w     = (const float*)d_in[14];
    const float* out_b     = (const float*)d_in[15];
    const float* spring_w0 = (const float*)d_in[16];
    const float* spring_b0 = (const float*)d_in[17];
    const float* spring_w1 = (const float*)d_in[18];
    const float* spring_b1 = (const float*)d_in[19];
    const float* joint_w0  = (const float*)d_in[20];
    const float* joint_b0  = (const float*)d_in[21];
    const float* joint_w1  = (const float*)d_in[22];
    const float* joint_b1  = (const float*)d_in[23];
    float* out = (float*)d_out;

    int nsm = 148;
    cudaDeviceGetAttribute(&nsm, cudaDevAttrMultiProcessorCount, 0);

    const int smem_b = B_TOTAL * sizeof(float);
    const int smem_m = M_TOTAL * sizeof(float);
    cudaFuncSetAttribute(ffp_branch, cudaFuncAttributeMaxDynamicSharedMemorySize, smem_b);
    cudaFuncSetAttribute(ffp_main,   cudaFuncAttributeMaxDynamicSharedMemorySize, smem_m);

    ffp_branch<<<64, 256, smem_b>>>(init_x, branch_w0, branch_b0, branch_ws, branch_bs, out_w);
    ffp_main<<<nsm, 256, smem_m>>>(init_x, query_x, init_v, query_v, init_av, query_av,
                                   trunk_w0, trunk_b0, trunk_ws, trunk_bs,
                                   out_b,
                                   spring_w0, spring_b0, spring_w1, spring_b1,
                                   joint_w0, joint_b0, joint_w1, joint_b1,
                                   out);
}

// round 6
// speedup vs baseline: 4.6336x; 3.7109x over previous
#include <cuda_runtime.h>
#include <math.h>
#include <stdint.h>

// ===========================================================================
// ForceFieldPredictor R5: warp-level mma.sync tf32 (HMMA fallback path).
// No tcgen05 (harness compiles PTX at base compute_103 target).
//
//  ffp_branch: fp32 (as R3) -> g_branchM[bo][k*3+j] = branch_out[k]*out_w[k][j]
//  ffp_main:   persistent, 256 thr, tile = 2 (b,o) = 128 rows.
//    trunk L0 (K=16pad), H1, H2 (K=128), joint L0 (K=16pad) via m16n8k8 tf32.
//    Weights tf32 in smem (XOR-swizzled, conflict-free scalar frag loads).
//    H2/joint consumed straight from fragments (shfl-reduced row dots).
// ===========================================================================

typedef unsigned long long ull;

// ---------------------------- small PTX helpers ----------------------------

__device__ __forceinline__ uint32_t f2tf32(float x) {
    uint32_t r; asm("cvt.rna.tf32.f32 %0, %1;" : "=r"(r) : "f"(x)); return r;
}
__device__ __forceinline__ float tf32f(float x) { return __uint_as_float(f2tf32(x)); }

__device__ __forceinline__ void mma8(float* d, const uint32_t* a, uint32_t b0, uint32_t b1) {
    asm volatile("mma.sync.aligned.m16n8k8.row.col.f32.tf32.tf32.f32 "
                 "{%0,%1,%2,%3}, {%4,%5,%6,%7}, {%8,%9}, {%0,%1,%2,%3};"
                 : "+f"(d[0]), "+f"(d[1]), "+f"(d[2]), "+f"(d[3])
                 : "r"(a[0]), "r"(a[1]), "r"(a[2]), "r"(a[3]), "r"(b0), "r"(b1));
}

// ------------------------- branch kernel (fp32, as R3) ---------------------

#define PADR 132
#define B_W     0
#define B_ACT0  16384
#define B_ACT1  (16384 + 64*PADR)
#define B_FEAT  (16384 + 2*64*PADR)
#define B_TOTAL (B_FEAT + 64*4)

__device__ float g_branchM[4096 * 384];   // [b*64+o][k*3+j]

#define FMA2(d, a, b) asm("fma.rn.f32x2 %0, %1, %2, %0;" : "+l"(d) : "l"(a), "l"(b))
#define SPLAT2(d, s)  asm("mov.b64 %0, {%1, %1};" : "=l"(d) : "r"(s))

__device__ __forceinline__ void stage_copy(float* dst, const float* src, int n, int tid)
{
    for (int i = tid * 4; i < n; i += 256 * 4)
        *(float4*)(dst + i) = *(const float4*)(src + i);
}

__device__ __forceinline__ void gemm_hidden_f2(const float* __restrict__ actIn,
                                               float* __restrict__ actOut,
                                               const float* __restrict__ sW,
                                               const float* __restrict__ bias_g,
                                               int ty, int tx, bool relu_in)
{
    const int r0 = ty * 4, c0 = tx * 8;
    ull acc[4][4];
    {
        ulonglong2 b0 = *(const ulonglong2*)(bias_g + c0);
        ulonglong2 b1 = *(const ulonglong2*)(bias_g + c0 + 4);
        #pragma unroll
        for (int i = 0; i < 4; i++) {
            acc[i][0] = b0.x; acc[i][1] = b0.y;
            acc[i][2] = b1.x; acc[i][3] = b1.y;
        }
    }
    for (int k = 0; k < 128; k += 4) {
        float4 av[4];
        #pragma unroll
        for (int i = 0; i < 4; i++) {
            float4 v = *(const float4*)(actIn + (r0 + i) * PADR + k);
            if (relu_in) {
                v.x = fmaxf(v.x, 0.f); v.y = fmaxf(v.y, 0.f);
                v.z = fmaxf(v.z, 0.f); v.w = fmaxf(v.w, 0.f);
            }
            av[i] = v;
        }
        #pragma unroll
        for (int kk = 0; kk < 4; kk++) {
            ulonglong2 w0 = *(const ulonglong2*)(sW + (k + kk) * 128 + c0);
            ulonglong2 w1 = *(const ulonglong2*)(sW + (k + kk) * 128 + c0 + 4);
            #pragma unroll
            for (int i = 0; i < 4; i++) {
                float a = (kk == 0) ? av[i].x : (kk == 1) ? av[i].y
                        : (kk == 2) ? av[i].z : av[i].w;
                ull a2;
                SPLAT2(a2, __float_as_uint(a));
                FMA2(acc[i][0], a2, w0.x);
                FMA2(acc[i][1], a2, w0.y);
                FMA2(acc[i][2], a2, w1.x);
                FMA2(acc[i][3], a2, w1.y);
            }
        }
    }
    #pragma unroll
    for (int i = 0; i < 4; i++) {
        ulonglong2 s0; s0.x = acc[i][0]; s0.y = acc[i][1];
        ulonglong2 s1; s1.x = acc[i][2]; s1.y = acc[i][3];
        *(ulonglong2*)(actOut + (r0 + i) * PADR + c0)     = s0;
        *(ulonglong2*)(actOut + (r0 + i) * PADR + c0 + 4) = s1;
    }
}

__device__ __forceinline__ void gemm_input(const float* __restrict__ feat, int fstride, int K,
                                           float* __restrict__ actOut,
                                           const float* __restrict__ sWin,
                                           const float* __restrict__ bias_g,
                                           int ty, int tx)
{
    const int r0 = ty * 4, c0 = tx * 8;
    float acc[4][8];
    float4 bv0 = *(const float4*)(bias_g + c0);
    float4 bv1 = *(const float4*)(bias_g + c0 + 4);
    #pragma unroll
    for (int i = 0; i < 4; i++) {
        acc[i][0] = bv0.x; acc[i][1] = bv0.y; acc[i][2] = bv0.z; acc[i][3] = bv0.w;
        acc[i][4] = bv1.x; acc[i][5] = bv1.y; acc[i][6] = bv1.z; acc[i][7] = bv1.w;
    }
    for (int k = 0; k < K; k++) {
        float4 w0 = *(const float4*)(sWin + k * 128 + c0);
        float4 w1 = *(const float4*)(sWin + k * 128 + c0 + 4);
        #pragma unroll
        for (int i = 0; i < 4; i++) {
            float a = feat[(r0 + i) * fstride + k];
            acc[i][0] = fmaf(a, w0.x, acc[i][0]);
            acc[i][1] = fmaf(a, w0.y, acc[i][1]);
            acc[i][2] = fmaf(a, w0.z, acc[i][2]);
            acc[i][3] = fmaf(a, w0.w, acc[i][3]);
            acc[i][4] = fmaf(a, w1.x, acc[i][4]);
            acc[i][5] = fmaf(a, w1.y, acc[i][5]);
            acc[i][6] = fmaf(a, w1.z, acc[i][6]);
            acc[i][7] = fmaf(a, w1.w, acc[i][7]);
        }
    }
    #pragma unroll
    for (int i = 0; i < 4; i++) {
        *(float4*)(actOut + (r0 + i) * PADR + c0)     = make_float4(acc[i][0], acc[i][1], acc[i][2], acc[i][3]);
        *(float4*)(actOut + (r0 + i) * PADR + c0 + 4) = make_float4(acc[i][4], acc[i][5], acc[i][6], acc[i][7]);
    }
}

__device__ __forceinline__ float segdist(float px, float py, float ax, float ay,
                                         float abx, float aby, float s)
{
    float t = ((px - ax) * abx + (py - ay) * aby) / s;
    t = fminf(fmaxf(t, 0.f), 1.f);
    float dx = px - (ax + t * abx);
    float dy = py - (ay + t * aby);
    return sqrtf(dx * dx + dy * dy);
}

extern "C" __global__ void __launch_bounds__(256, 1)
ffp_branch(const float* __restrict__ init_x,
           const float* __restrict__ branch_w0, const float* __restrict__ branch_b0,
           const float* __restrict__ branch_ws, const float* __restrict__ branch_bs,
           const float* __restrict__ out_w)
{
    extern __shared__ float sm[];
    float* sW   = sm + B_W;
    float* act0 = sm + B_ACT0;
    float* act1 = sm + B_ACT1;
    float* feat = sm + B_FEAT;
    const int tid = threadIdx.x, ty = tid >> 4, tx = tid & 15;
    const int b = blockIdx.x;

    stage_copy(sW, branch_w0 + 2 * 128, 384, tid);
    if (tid < 64) {
        const float* ix = init_x + (b * 64 + tid) * 9;
        feat[tid * 4 + 0] = ix[2];
        feat[tid * 4 + 1] = ix[3];
        feat[tid * 4 + 2] = ix[4];
    }
    __syncthreads();
    gemm_input(feat, 4, 3, act0, sW, branch_b0, ty, tx);
    __syncthreads();
    stage_copy(sW, branch_ws, 16384, tid);
    __syncthreads();
    gemm_hidden_f2(act0, act1, sW, branch_bs, ty, tx, true);
    __syncthreads();
    stage_copy(sW, branch_ws + 16384, 16384, tid);
    __syncthreads();
    gemm_hidden_f2(act1, act0, sW, branch_bs + 128, ty, tx, true);
    __syncthreads();

    for (int idx = tid; idx < 64 * 384; idx += 256) {
        int o = idx / 384;
        int r = idx - o * 384;
        int k = r / 3;
        int j = r - k * 3;
        g_branchM[(b * 64 + o) * 384 + r] = act0[o * PADR + k] * out_w[k * 3 + j];
    }
}

// ------------------------------- main kernel -------------------------------
// smem layout (float offsets)
#define S_W1    0                 // 16384 : trunk H1, tf32, swizzled [n][k]
#define S_W2    16384             // 16384 : trunk H2
#define S_ACT   32768             // 16896 : activations, stride 132
                                  //   featT aliases S_ACT+0     (stride 20, 2560)
                                  //   featJ aliases S_ACT+2560  (stride 20, 2560)
#define S_W0T   49664             // 2304 : trunk W0t [n][k], stride 18, tf32
#define S_JW0T  51968             // 2304 : joint W0t
#define S_B0    54272
#define S_B1    54400
#define S_B2    54528
#define S_JB0   54656
#define S_JW1   54784             // 256 : [part][128]
#define S_MSH   55040             // 768 : tile*384 + part*128 + k
#define S_SCR   55808             // 1280: row*10 + wc*5 + {p0..p4}
#define S_TOTAL 57088             // 228,352 B

#define ASTR 132                  // activation row stride
#define FSTR 20                   // feature row stride
#define WSTR 18                   // input-weight row stride

// d layout: d[rb*8+nt][4]
__device__ __forceinline__ void layer_hidden(const float* __restrict__ sW,
                                             const float* __restrict__ act,
                                             float (*d)[4],
                                             int wr, int wc, int g, int t4)
{
    #pragma unroll
    for (int i = 0; i < 16; i++)
        d[i][0] = d[i][1] = d[i][2] = d[i][3] = 0.f;
    const float* a0p = act + (wr * 32 + g) * ASTR + t4;
    const float* b0p = sW + (wc * 64 + g) * 128 + t4;
    #pragma unroll 4
    for (int c = 0; c < 16; c++) {
        uint32_t A[2][4];
        #pragma unroll
        for (int rb = 0; rb < 2; rb++) {
            const float* ap = a0p + rb * 16 * ASTR + c * 8;
            A[rb][0] = __float_as_uint(ap[0]);
            A[rb][1] = __float_as_uint(ap[8 * ASTR]);
            A[rb][2] = __float_as_uint(ap[4]);
            A[rb][3] = __float_as_uint(ap[8 * ASTR + 4]);
        }
        const int w0 = ((2 * c) ^ g) << 2;
        const int w1 = ((2 * c + 1) ^ g) << 2;
        #pragma unroll
        for (int nt = 0; nt < 8; nt++) {
            const float* bp = b0p + nt * 8 * 128;
            uint32_t b0 = __float_as_uint(bp[w0]);
            uint32_t b1 = __float_as_uint(bp[w1]);
            mma8(d[nt],     A[0], b0, b1);
            mma8(d[8 + nt], A[1], b0, b1);
        }
    }
}

__device__ __forceinline__ void layer_input(const float* __restrict__ sWin,
                                            const float* __restrict__ feat,
                                            float (*d)[4],
                                            int wr, int wc, int g, int t4)
{
    #pragma unroll
    for (int i = 0; i < 16; i++)
        d[i][0] = d[i][1] = d[i][2] = d[i][3] = 0.f;
    const float* a0p = feat + (wr * 32 + g) * FSTR + t4;
    const float* b0p = sWin + (wc * 64 + g) * WSTR + t4;
    #pragma unroll
    for (int c = 0; c < 2; c++) {
        uint32_t A[2][4];
        #pragma unroll
        for (int rb = 0; rb < 2; rb++) {
            const float* ap = a0p + rb * 16 * FSTR + c * 8;
            A[rb][0] = __float_as_uint(ap[0]);
            A[rb][1] = __float_as_uint(ap[8 * FSTR]);
            A[rb][2] = __float_as_uint(ap[4]);
            A[rb][3] = __float_as_uint(ap[8 * FSTR + 4]);
        }
        #pragma unroll
        for (int nt = 0; nt < 8; nt++) {
            const float* bp = b0p + nt * 8 * WSTR + c * 8;
            uint32_t b0 = __float_as_uint(bp[0]);
            uint32_t b1 = __float_as_uint(bp[4]);
            mma8(d[nt],     A[0], b0, b1);
            mma8(d[8 + nt], A[1], b0, b1);
        }
    }
}

// relu(d + bias) -> tf32 -> act
__device__ __forceinline__ void writeback(float (*d)[4], float* __restrict__ act,
                                          const float* __restrict__ bias,
                                          int wr, int wc, int g, int t4)
{
    #pragma unroll
    for (int rb = 0; rb < 2; rb++) {
        const int r = wr * 32 + rb * 16 + g;
        #pragma unroll
        for (int nt = 0; nt < 8; nt++) {
            const int col = wc * 64 + nt * 8 + t4 * 2;
            float2 bb = *(const float2*)(bias + col);
            float* p = act + r * ASTR + col;
            const float* dd = d[rb * 8 + nt];
            p[0] = tf32f(fmaxf(dd[0] + bb.x, 0.f));
            p[1] = tf32f(fmaxf(dd[1] + bb.y, 0.f));
            p[8 * ASTR]     = tf32f(fmaxf(dd[2] + bb.x, 0.f));
            p[8 * ASTR + 1] = tf32f(fmaxf(dd[3] + bb.y, 0.f));
        }
    }
}

extern "C" __global__ void __launch_bounds__(256, 1)
ffp_main(const float* __restrict__ init_x,  const float* __restrict__ query_x,
         const float* __restrict__ init_v,  const float* __restrict__ query_v,
         const float* __restrict__ init_av, const float* __restrict__ query_av,
         const float* __restrict__ trunk_w0, const float* __restrict__ trunk_b0,
         const float* __restrict__ trunk_ws, const float* __restrict__ trunk_bs,
         const float* __restrict__ out_b,
         const float* __restrict__ spring_w0, const float* __restrict__ spring_b0,
         const float* __restrict__ spring_w1, const float* __restrict__ spring_b1,
         const float* __restrict__ joint_w0, const float* __restrict__ joint_b0,
         const float* __restrict__ joint_w1, const float* __restrict__ joint_b1,
         float* __restrict__ out)
{
    extern __shared__ float sm[];
    float* act   = sm + S_ACT;
    float* featT = sm + S_ACT;          // aliases act (released at L0 writeback)
    float* featJ = sm + S_ACT + 2560;
    float* msh   = sm + S_MSH;
    float* scr   = sm + S_SCR;
    const int tid = threadIdx.x;
    const int wid = tid >> 5, lane = tid & 31;
    const int wr = wid & 3, wc = wid >> 2;
    const int g = lane >> 2, t4 = lane & 3;

    // ---- one-time weight staging (tf32) ----
    for (int i = tid * 4; i < 4608; i += 1024)
        *(float4*)(sm + S_W0T + i) = make_float4(0.f, 0.f, 0.f, 0.f);
    __syncthreads();
    for (int idx = tid; idx < 16384; idx += 256) {
        int k = idx >> 7, n = idx & 127;
        int f = n * 128 + (((k >> 2) ^ (n & 7)) << 2) + (k & 3);
        sm[S_W1 + f] = tf32f(trunk_ws[idx]);
        sm[S_W2 + f] = tf32f(trunk_ws[16384 + idx]);
    }
    for (int idx = tid; idx < 9 * 128; idx += 256) {
        int k = idx >> 7, n = idx & 127;
        sm[S_W0T + n * WSTR + k] = tf32f(trunk_w0[idx]);
    }
    for (int idx = tid; idx < 15 * 128; idx += 256) {
        int k = idx >> 7, n = idx & 127;
        sm[S_JW0T + n * WSTR + k] = tf32f(joint_w0[idx]);
    }
    for (int i = tid; i < 128; i += 256) {
        sm[S_B0 + i]  = trunk_b0[i];
        sm[S_B1 + i]  = trunk_bs[i];
        sm[S_B2 + i]  = trunk_bs[128 + i];
        sm[S_JB0 + i] = joint_b0[i];
    }
    if (tid < 256) sm[S_JW1 + tid] = joint_w1[(tid & 127) * 2 + (tid >> 7)];
    __syncthreads();

    for (int pp = blockIdx.x; pp < 2048; pp += gridDim.x) {
        const int bo0 = pp << 1;

        // stage msh planar: tile*384 + part*128 + k
        for (int d0 = tid; d0 < 768; d0 += 256) {
            int tile = d0 / 384, rr = d0 - tile * 384;
            int part = rr >> 7, k = rr & 127;
            msh[d0] = g_branchM[(bo0 + tile) * 384 + k * 3 + part];
        }

        // ---- features (tid<128), masks kept in registers ----
        float relx = 0.f, rely = 0.f, maskD = 0.f, maskJ = 0.f, maskS = 0.f;
        if (tid < 128) {
            const int r = tid, tile = r >> 6, t = r & 63;
            const int bo = bo0 + tile, b = bo >> 6;
            const float* ix = init_x + bo * 9;
            const float* qx = query_x + (b * 64 + t) * 9;
            float i2 = ix[2], i3 = ix[3], i4 = ix[4], i7 = ix[7], i8 = ix[8];
            float q2 = qx[2], q3 = qx[3], q4 = qx[4], q7 = qx[7], q8 = qx[8];
            relx = qx[0] - ix[0]; rely = qx[1] - ix[1];
            float qvx = query_v[(b * 64 + t) * 2 + 0] - init_v[bo * 2 + 0];
            float qvy = query_v[(b * 64 + t) * 2 + 1] - init_v[bo * 2 + 1];
            float iav = init_av[bo];
            float qav = query_av[b * 64 + t] - iav;

            float sn1, cs1; sincosf(i3 * 100.f, &sn1, &cs1);
            float sn2, cs2; sincosf(q3 * 100.f, &sn2, &cs2);
            float o1x = i2 * 0.5f * cs1, o1y = i2 * 0.5f * sn1;
            float o2x = q2 * 0.5f * cs2, o2y = q2 * 0.5f * sn2;
            float ab1x = 2.f * o1x, ab1y = 2.f * o1y;
            float ab2x = 2.f * o2x, ab2y = 2.f * o2y;
            float ss1 = ab1x * ab1x + ab1y * ab1y + 1e-8f;
            float ss2 = ab2x * ab2x + ab2y * ab2y + 1e-8f;
            float A2x = relx - o2x, A2y = rely - o2y;
            float B2x = relx + o2x, B2y = rely + o2y;
            float d1 = segdist(A2x, A2y, -o1x, -o1y, ab1x, ab1y, ss1);
            float d2 = segdist(B2x, B2y, -o1x, -o1y, ab1x, ab1y, ss1);
            float d3 = segdist(-o1x, -o1y, A2x, A2y, ab2x, ab2y, ss2);
            float d4 = segdist(o1x, o1y, A2x, A2y, ab2x, ab2y, ss2);
            float dist = fminf(fminf(d1, d2), fminf(d3, d4)) - i4 - q4;
            maskD = (dist <= 0.f) ? 1.f : 0.f;
            float ti = truncf(i7), tq = truncf(q7);
            maskJ = (ti == tq && i7 > 0.f) ? 1.f : 0.f;
            maskS = (i8 == q8 && i8 > 0.f) ? 1.f : 0.f;

            uint32_t ft[16], fj[16];
            ft[0] = f2tf32(relx); ft[1] = f2tf32(rely);
            ft[2] = f2tf32(q2);   ft[3] = f2tf32(q3);  ft[4] = f2tf32(q4);
            ft[5] = f2tf32(qvx);  ft[6] = f2tf32(qvy); ft[7] = f2tf32(qav);
            ft[8] = f2tf32(dist * maskD * 100.f);
            #pragma unroll
            for (int j = 9; j < 16; j++) ft[j] = 0u;
            fj[0] = 0u; fj[1] = 0u;
            fj[2] = f2tf32(i2);  fj[3] = f2tf32(i3);  fj[4] = f2tf32(i4);
            fj[5] = ft[0]; fj[6] = ft[1];
            fj[7] = ft[2]; fj[8] = ft[3]; fj[9] = ft[4];
            fj[10] = ft[5]; fj[11] = ft[6];
            fj[12] = f2tf32(iav); fj[13] = ft[7];
            fj[14] = f2tf32(i7 - ti); fj[15] = 0u;
            #pragma unroll
            for (int j = 0; j < 4; j++) {
                *(float4*)(featT + r * FSTR + j * 4) = *(float4*)(ft + j * 4);
                *(float4*)(featJ + r * FSTR + j * 4) = *(float4*)(fj + j * 4);
            }
        }
        __syncthreads();   // (1) features + msh ready

        float d[16][4];

        // ---- joint L0 + fused epilogue partials (p3, p4) ----
        {
            layer_input(sm + S_JW0T, featJ, d, wr, wc, g, t4);
            float pj[4][2];
            #pragma unroll
            for (int q = 0; q < 4; q++) pj[q][0] = pj[q][1] = 0.f;
            #pragma unroll
            for (int rb = 0; rb < 2; rb++)
            #pragma unroll
            for (int nt = 0; nt < 8; nt++) {
                const int col = wc * 64 + nt * 8 + 2 * t4;
                float2 jb = *(const float2*)(sm + S_JB0 + col);
                float2 w0v = *(const float2*)(sm + S_JW1 + col);
                float2 w1v = *(const float2*)(sm + S_JW1 + 128 + col);
                const float* dd = d[rb * 8 + nt];
                float h0 = fmaxf(dd[0] + jb.x, 0.f), h1 = fmaxf(dd[1] + jb.y, 0.f);
                float h2 = fmaxf(dd[2] + jb.x, 0.f), h3 = fmaxf(dd[3] + jb.y, 0.f);
                pj[rb * 2][0]     += h0 * w0v.x + h1 * w0v.y;
                pj[rb * 2][1]     += h0 * w1v.x + h1 * w1v.y;
                pj[rb * 2 + 1][0] += h2 * w0v.x + h3 * w0v.y;
                pj[rb * 2 + 1][1] += h2 * w1v.x + h3 * w1v.y;
            }
            #pragma unroll
            for (int q = 0; q < 4; q++)
            #pragma unroll
            for (int j = 0; j < 2; j++) {
                float v = pj[q][j];
                v += __shfl_xor_sync(0xffffffffu, v, 1);
                v += __shfl_xor_sync(0xffffffffu, v, 2);
                if (t4 == 0) {
                    int row = wr * 32 + (q >> 1) * 16 + g + (q & 1) * 8;
                    scr[row * 10 + wc * 5 + 3 + j] = v;
                }
            }
        }

        // ---- trunk L0 ----
        layer_input(sm + S_W0T, featT, d, wr, wc, g, t4);
        __syncthreads();   // (2) feat reads done; act region may be overwritten
        writeback(d, act, sm + S_B0, wr, wc, g, t4);
        __syncthreads();   // (3)

        // ---- trunk H1 ----
        layer_hidden(sm + S_W1, act, d, wr, wc, g, t4);
        __syncthreads();   // (4)
        writeback(d, act, sm + S_B1, wr, wc, g, t4);
        __syncthreads();   // (5)

        // ---- trunk H2 + fused epilogue partials (p0..p2) ----
        layer_hidden(sm + S_W2, act, d, wr, wc, g, t4);
        {
            const float* mb = msh + (wr >> 1) * 384;
            float p[4][3];
            #pragma unroll
            for (int q = 0; q < 4; q++) p[q][0] = p[q][1] = p[q][2] = 0.f;
            #pragma unroll
            for (int rb = 0; rb < 2; rb++)
            #pragma unroll
            for (int nt = 0; nt < 8; nt++) {
                const int col = wc * 64 + nt * 8 + 2 * t4;
                float2 bb = *(const float2*)(sm + S_B2 + col);
                float2 m0 = *(const float2*)(mb + col);
                float2 m1 = *(const float2*)(mb + 128 + col);
                float2 m2 = *(const float2*)(mb + 256 + col);
                const float* dd = d[rb * 8 + nt];
                float h0 = dd[0] + bb.x, h1 = dd[1] + bb.y;
                float h2 = dd[2] + bb.x, h3 = dd[3] + bb.y;
                p[rb * 2][0]     += h0 * m0.x + h1 * m0.y;
                p[rb * 2][1]     += h0 * m1.x + h1 * m1.y;
                p[rb * 2][2]     += h0 * m2.x + h1 * m2.y;
                p[rb * 2 + 1][0] += h2 * m0.x + h3 * m0.y;
                p[rb * 2 + 1][1] += h2 * m1.x + h3 * m1.y;
                p[rb * 2 + 1][2] += h2 * m2.x + h3 * m2.y;
            }
            #pragma unroll
            for (int q = 0; q < 4; q++)
            #pragma unroll
            for (int j = 0; j < 3; j++) {
                float v = p[q][j];
                v += __shfl_xor_sync(0xffffffffu, v, 1);
                v += __shfl_xor_sync(0xffffffffu, v, 2);
                if (t4 == 0) {
                    int row = wr * 32 + (q >> 1) * 16 + g + (q & 1) * 8;
                    scr[row * 10 + wc * 5 + j] = v;
                }
            }
        }
        __syncthreads();   // (6) all scr partials in place

        // ---- combine + masks + spring + store ----
        if (tid < 128) {
            const int r = tid, tile = r >> 6, t = r & 63;
            const int bo = bo0 + tile;
            const float* s = scr + r * 10;
            float f0 = (s[0] + s[5] + out_b[0]) * maskD;
            float f1 = (s[1] + s[6] + out_b[1]) * maskD;
            float f2 = (s[2] + s[7] + out_b[2]) * maskD;
            if (maskJ > 0.f) {
                f0 += s[3] + s[8] + joint_b1[0];
                f1 += s[4] + s[9] + joint_b1[1];
            }
            if (maskS > 0.f) {
                float len = sqrtf(relx * relx + rely * rely);
                float sf = spring_b1[0];
                for (int k = 0; k < 128; k++)
                    sf = fmaf(fmaxf(fmaf(len, spring_w0[k], spring_b0[k]), 0.f),
                              spring_w1[k], sf);
                float inv = 1.f / (len + 1e-8f);
                f0 = fmaf(sf, -relx * inv, f0);
                f1 = fmaf(sf, -rely * inv, f1);
            }
            float* op = out + (bo * 64 + t) * 3;
            op[0] = f0; op[1] = f1; op[2] = f2;
        }
        __syncthreads();   // (7) protect msh/feat/scr for next iteration
    }
}

// ---------------------------------------------------------------------------

extern "C" void kernel_launch(void* const* d_in, const int* in_sizes, int n_in,
                              void* d_out, int out_size)
{
    const float* init_x    = (const float*)d_in[0];
    const float* query_x   = (const float*)d_in[1];
    const float* init_v    = (const float*)d_in[2];
    const float* query_v   = (const float*)d_in[3];
    const float* init_av   = (const float*)d_in[4];
    const float* query_av  = (const float*)d_in[5];
    const float* trunk_w0  = (const float*)d_in[6];
    const float* trunk_b0  = (const float*)d_in[7];
    const float* trunk_ws  = (const float*)d_in[8];
    const float* trunk_bs  = (const float*)d_in[9];
    const float* branch_w0 = (const float*)d_in[10];
    const float* branch_b0 = (const float*)d_in[11];
    const float* branch_ws = (const float*)d_in[12];
    const float* branch_bs = (const float*)d_in[13];
    const float* out_w     = (const float*)d_in[14];
    const float* out_b     = (const float*)d_in[15];
    const float* spring_w0 = (const float*)d_in[16];
    const float* spring_b0 = (const float*)d_in[17];
    const float* spring_w1 = (const float*)d_in[18];
    const float* spring_b1 = (const float*)d_in[19];
    const float* joint_w0  = (const float*)d_in[20];
    const float* joint_b0  = (const float*)d_in[21];
    const float* joint_w1  = (const float*)d_in[22];
    const float* joint_b1  = (const float*)d_in[23];
    float* out = (float*)d_out;

    int nsm = 148;
    cudaDeviceGetAttribute(&nsm, cudaDevAttrMultiProcessorCount, 0);

    const int smem_b = B_TOTAL * sizeof(float);
    const int smem_m = S_TOTAL * sizeof(float);
    cudaFuncSetAttribute(ffp_branch, cudaFuncAttributeMaxDynamicSharedMemorySize, smem_b);
    cudaFuncSetAttribute(ffp_main,   cudaFuncAttributeMaxDynamicSharedMemorySize, smem_m);

    ffp_branch<<<64, 256, smem_b>>>(init_x, branch_w0, branch_b0, branch_ws, branch_bs, out_w);
    ffp_main<<<nsm, 256, smem_m>>>(init_x, query_x, init_v, query_v, init_av, query_av,
                                   trunk_w0, trunk_b0, trunk_ws, trunk_bs,
                                   out_b,
                                   spring_w0, spring_b0, spring_w1, spring_b1,
                                   joint_w0, joint_b0, joint_w1, joint_b1,
                                   out);
}